// round 6
// baseline (speedup 1.0000x reference)
#include <cuda_runtime.h>

// Shifted Window Attention (Swin): B=16, H=W=56, C=384, window 7x7, shift 3,
// heads=12, hd=32.  No padding (56 % 7 == 0).  nW=64 windows/img, 1024 total.
//
// Pipeline:
//   setup_kernel : g_rowbase[m] = x-offset of (shifted) window token m
//   gemm<0>      : QKV = gather(x) @ qkv_w^T + b  -> Q,K,V [win,head,49,32] (q scaled)
//   attn_kernel  : per (win,head): S=QK^T + relbias + mask, softmax, O=S V
//   gemm<1>      : out = scatter( O @ proj_w^T + b )   (merge + inverse roll)

#define M_TOT   50176            // 1024 * 49
#define QKV_ONE 19267584ULL      // 1024*12*49*32
#define Q_SCALE 0.17677669529663687f   // 32^-0.5

__device__ float g_qkv[3ULL * QKV_ONE];          // Q | K | V
__device__ float g_attn[(size_t)M_TOT * 384];    // attention output, [m, C]
__device__ int   g_rowbase[M_TOT];

// ---------------------------------------------------------------------------
__global__ void setup_kernel() {
    int m = blockIdx.x * 256 + threadIdx.x;
    if (m >= M_TOT) return;
    int b   = m / 3136;
    int rem = m - b * 3136;
    int win = rem / 49;
    int n   = rem - win * 49;
    int wi = win >> 3, wj = win & 7;
    int r = n / 7, c = n - r * 7;
    int hh = wi * 7 + r + 3; if (hh >= 56) hh -= 56;
    int ww = wj * 7 + c + 3; if (ww >= 56) ww -= 56;
    g_rowbase[m] = ((b * 56 + hh) * 56 + ww) * 384;
}

// ---------------------------------------------------------------------------
// SGEMM: C[M,N] = A[M,K] * W[N,K]^T + bias, K=384, BM=BN=128, BK=8, 8x8 uTile.
// MODE 0: A = gather rows of x via g_rowbase; out -> Q/K/V layout (q scaled).
// MODE 1: A = g_attn (dense); out -> scatter via g_rowbase (+oc), proj bias.
template <int MODE>
__global__ __launch_bounds__(256, 2)
void gemm_kernel(const float* __restrict__ A,
                 const float* __restrict__ W,
                 const float* __restrict__ bias,
                 float* __restrict__ outp)
{
    __shared__ __align__(16) float As[2][8 * 132];
    __shared__ __align__(16) float Bs[2][8 * 132];

    const int tid = threadIdx.x;
    const int bx = blockIdx.x, by = blockIdx.y;

    // ---- load lanes ----
    const int arow = tid >> 1;            // 0..127
    const int ak   = (tid & 1) << 2;      // 0 or 4
    const int m_load = by * 128 + arow;

    const float* aptr;
    if (MODE == 0) aptr = A + g_rowbase[m_load] + ak;
    else           aptr = g_attn + (size_t)m_load * 384 + ak;
    const float* bptr = W + (size_t)(bx * 128 + arow) * 384 + ak;

    // prologue: tile 0
    {
        float4 av = *(const float4*)aptr;
        float4 bv = *(const float4*)bptr;
        As[0][(ak + 0) * 132 + arow] = av.x;
        As[0][(ak + 1) * 132 + arow] = av.y;
        As[0][(ak + 2) * 132 + arow] = av.z;
        As[0][(ak + 3) * 132 + arow] = av.w;
        Bs[0][(ak + 0) * 132 + arow] = bv.x;
        Bs[0][(ak + 1) * 132 + arow] = bv.y;
        Bs[0][(ak + 2) * 132 + arow] = bv.z;
        Bs[0][(ak + 3) * 132 + arow] = bv.w;
    }
    __syncthreads();

    // ---- compute lanes ----
    const int cr = tid >> 4;   // 0..15
    const int cc = tid & 15;   // 0..15
    const int r0 = cr * 4;
    const int c0 = cc * 4;

    float acc[8][8];
#pragma unroll
    for (int i = 0; i < 8; i++)
#pragma unroll
        for (int j = 0; j < 8; j++) acc[i][j] = 0.0f;

    int buf = 0;
    for (int kt = 8; kt <= 384; kt += 8) {
        const bool more = (kt < 384);
        float4 na, nb;
        if (more) {
            na = *(const float4*)(aptr + kt);
            nb = *(const float4*)(bptr + kt);
        }
#pragma unroll
        for (int k = 0; k < 8; k++) {
            float4 a0 = *(const float4*)&As[buf][k * 132 + r0];
            float4 a1 = *(const float4*)&As[buf][k * 132 + r0 + 64];
            float4 b0 = *(const float4*)&Bs[buf][k * 132 + c0];
            float4 b1 = *(const float4*)&Bs[buf][k * 132 + c0 + 64];
            float ar[8] = {a0.x, a0.y, a0.z, a0.w, a1.x, a1.y, a1.z, a1.w};
            float br[8] = {b0.x, b0.y, b0.z, b0.w, b1.x, b1.y, b1.z, b1.w};
#pragma unroll
            for (int i = 0; i < 8; i++)
#pragma unroll
                for (int j = 0; j < 8; j++) acc[i][j] += ar[i] * br[j];
        }
        if (more) {
            int nbuf = buf ^ 1;
            As[nbuf][(ak + 0) * 132 + arow] = na.x;
            As[nbuf][(ak + 1) * 132 + arow] = na.y;
            As[nbuf][(ak + 2) * 132 + arow] = na.z;
            As[nbuf][(ak + 3) * 132 + arow] = na.w;
            Bs[nbuf][(ak + 0) * 132 + arow] = nb.x;
            Bs[nbuf][(ak + 1) * 132 + arow] = nb.y;
            Bs[nbuf][(ak + 2) * 132 + arow] = nb.z;
            Bs[nbuf][(ak + 3) * 132 + arow] = nb.w;
            __syncthreads();
            buf = nbuf;
        }
    }

    // ---- epilogue ----
#pragma unroll
    for (int ii = 0; ii < 8; ii++) {
        int row = r0 + (ii & 3) + ((ii >> 2) << 6);
        int m = by * 128 + row;
        int win = 0, n = 0;
        if (MODE == 0) { win = m / 49; n = m - win * 49; }
#pragma unroll
        for (int jj = 0; jj < 2; jj++) {
            int oc = bx * 128 + c0 + jj * 64;
            float4 bb = *(const float4*)&bias[oc];
            float4 o;
            o.x = acc[ii][jj * 4 + 0] + bb.x;
            o.y = acc[ii][jj * 4 + 1] + bb.y;
            o.z = acc[ii][jj * 4 + 2] + bb.z;
            o.w = acc[ii][jj * 4 + 3] + bb.w;
            if (MODE == 0) {
                int which = oc / 384;
                int remo = oc - which * 384;
                int head = remo >> 5;
                int d0 = remo & 31;
                if (which == 0) {
                    o.x *= Q_SCALE; o.y *= Q_SCALE; o.z *= Q_SCALE; o.w *= Q_SCALE;
                }
                float* dst = g_qkv + (size_t)which * QKV_ONE
                           + ((size_t)(win * 12 + head) * 49 + n) * 32 + d0;
                *(float4*)dst = o;
            } else {
                float* dst = outp + g_rowbase[m] + oc;
                *(float4*)dst = o;
            }
        }
    }
}

// ---------------------------------------------------------------------------
// Per (window, head) attention. blockIdx.x = win*12 + head, 256 threads.
__global__ __launch_bounds__(256)
void attn_kernel(const float* __restrict__ table)
{
    __shared__ float Qs[1568], Ks[1568], Vs[1568];
    __shared__ float S[49 * 52];
    __shared__ float tbl[169];
    __shared__ int   ids[49];

    const int tid = threadIdx.x;
    const int bid = blockIdx.x;
    const int win = bid / 12;          // GLOBAL window index (0..1023)
    const int head = bid - win * 12;

    const size_t base = (size_t)bid * 1568;   // (win*12+head)*1568
    const float4* q4 = (const float4*)(g_qkv + base);
    const float4* k4 = (const float4*)(g_qkv + QKV_ONE + base);
    const float4* v4 = (const float4*)(g_qkv + 2 * QKV_ONE + base);
    for (int i = tid; i < 392; i += 256) {
        ((float4*)Qs)[i] = q4[i];
        ((float4*)Ks)[i] = k4[i];
        ((float4*)Vs)[i] = v4[i];
    }
    if (tid < 169) tbl[tid] = table[tid * 12 + head];
    if (tid < 49) {
        // FIX: region ids need the LOCAL window index within the image.
        // win is global (b*64 + wi*8 + wj); previously wi = win>>3 gave
        // b*8 + wi_local, destroying the row-region mask for all b >= 1.
        int winl = win & 63;               // local window 0..63
        int wi = winl >> 3, wj = winl & 7;
        int r = tid / 7, c = tid - r * 7;
        int hh = wi * 7 + r, ww = wj * 7 + c;
        int rh = (hh < 49) ? 0 : ((hh < 53) ? 1 : 2);
        int rw = (ww < 49) ? 0 : ((ww < 53) ? 1 : 2);
        ids[tid] = rh * 3 + rw;
    }
    __syncthreads();

    // S = Q K^T + relbias + mask
    for (int idx = tid; idx < 2401; idx += 256) {
        int i = idx / 49, j = idx - i * 49;
        const float* qi = &Qs[i * 32];
        const float* kj = &Ks[j * 32];
        float s = 0.0f;
#pragma unroll
        for (int d = 0; d < 32; d++) s += qi[d] * kj[d];
        int r1 = i / 7, c1 = i - r1 * 7;
        int r2 = j / 7, c2 = j - r2 * 7;
        s += tbl[(r1 - r2 + 6) * 13 + (c1 - c2 + 6)];
        if (ids[i] != ids[j]) s -= 100.0f;
        S[i * 52 + j] = s;
    }
    __syncthreads();

    // softmax: one warp per row
    const int warp = tid >> 5, lane = tid & 31;
    for (int row = warp; row < 49; row += 8) {
        float v0 = S[row * 52 + lane];
        float v1 = (lane < 17) ? S[row * 52 + 32 + lane] : -1e30f;
        float mx = fmaxf(v0, v1);
#pragma unroll
        for (int off = 16; off; off >>= 1)
            mx = fmaxf(mx, __shfl_xor_sync(0xffffffffu, mx, off));
        float e0 = __expf(v0 - mx);
        float e1 = (lane < 17) ? __expf(v1 - mx) : 0.0f;
        float sm = e0 + e1;
#pragma unroll
        for (int off = 16; off; off >>= 1)
            sm += __shfl_xor_sync(0xffffffffu, sm, off);
        float inv = 1.0f / sm;
        S[row * 52 + lane] = e0 * inv;
        if (lane < 17) S[row * 52 + 32 + lane] = e1 * inv;
    }
    __syncthreads();

    // O = S V  -> g_attn[(win*49+i)*384 + head*32 + d]
    for (int idx = tid; idx < 1568; idx += 256) {
        int i = idx >> 5, d = idx & 31;
        float s = 0.0f;
#pragma unroll 7
        for (int j = 0; j < 49; j++) s += S[i * 52 + j] * Vs[j * 32 + d];
        g_attn[((size_t)win * 49 + i) * 384 + head * 32 + d] = s;
    }
}

// ---------------------------------------------------------------------------
extern "C" void kernel_launch(void* const* d_in, const int* in_sizes, int n_in,
                              void* d_out, int out_size)
{
    const float* x      = (const float*)d_in[0];
    const float* qkv_w  = (const float*)d_in[1];
    const float* qkv_b  = (const float*)d_in[2];
    const float* proj_w = (const float*)d_in[3];
    const float* proj_b = (const float*)d_in[4];
    const float* table  = (const float*)d_in[5];
    float* out = (float*)d_out;

    setup_kernel<<<(M_TOT + 255) / 256, 256>>>();
    gemm_kernel<0><<<dim3(9, 392), 256>>>(x, qkv_w, qkv_b, nullptr);
    attn_kernel<<<12288, 256>>>(table);
    gemm_kernel<1><<<dim3(3, 392), 256>>>(nullptr, proj_w, proj_b, out);
}

// round 8
// speedup vs baseline: 1.5992x; 1.5992x over previous
#include <cuda_runtime.h>

// Shifted Window Attention (Swin): B=16, H=W=56, C=384, window 7x7, shift 3,
// heads=12, hd=32.  No padding (56 % 7 == 0).  nW=64 windows/img, 1024 total.

#define M_TOT   50176            // 1024 * 49
#define QKV_ONE 19267584ULL      // 1024*12*49*32
#define Q_SCALE 0.17677669529663687f   // 32^-0.5

__device__ float g_qkv[3ULL * QKV_ONE];          // Q | K | V
__device__ float g_attn[(size_t)M_TOT * 384];    // attention output, [m, C]
__device__ int   g_rowbase[M_TOT];

// ---------------------------------------------------------------------------
__global__ void setup_kernel() {
    int m = blockIdx.x * 256 + threadIdx.x;
    if (m >= M_TOT) return;
    int b   = m / 3136;
    int rem = m - b * 3136;
    int win = rem / 49;
    int n   = rem - win * 49;
    int wi = win >> 3, wj = win & 7;
    int r = n / 7, c = n - r * 7;
    int hh = wi * 7 + r + 3; if (hh >= 56) hh -= 56;
    int ww = wj * 7 + c + 3; if (ww >= 56) ww -= 56;
    g_rowbase[m] = ((b * 56 + hh) * 56 + ww) * 384;
}

// ---------------------------------------------------------------------------
// SGEMM: C[M,N] = A[M,K] * W[N,K]^T + bias, K=384, BM=BN=128, BK=8, 8x8 uTile.
template <int MODE>
__global__ __launch_bounds__(256, 2)
void gemm_kernel(const float* __restrict__ A,
                 const float* __restrict__ W,
                 const float* __restrict__ bias,
                 float* __restrict__ outp)
{
    __shared__ __align__(16) float As[2][8 * 132];
    __shared__ __align__(16) float Bs[2][8 * 132];

    const int tid = threadIdx.x;
    const int bx = blockIdx.x, by = blockIdx.y;

    const int arow = tid >> 1;
    const int ak   = (tid & 1) << 2;
    const int m_load = by * 128 + arow;

    const float* aptr;
    if (MODE == 0) aptr = A + g_rowbase[m_load] + ak;
    else           aptr = g_attn + (size_t)m_load * 384 + ak;
    const float* bptr = W + (size_t)(bx * 128 + arow) * 384 + ak;

    {
        float4 av = *(const float4*)aptr;
        float4 bv = *(const float4*)bptr;
        As[0][(ak + 0) * 132 + arow] = av.x;
        As[0][(ak + 1) * 132 + arow] = av.y;
        As[0][(ak + 2) * 132 + arow] = av.z;
        As[0][(ak + 3) * 132 + arow] = av.w;
        Bs[0][(ak + 0) * 132 + arow] = bv.x;
        Bs[0][(ak + 1) * 132 + arow] = bv.y;
        Bs[0][(ak + 2) * 132 + arow] = bv.z;
        Bs[0][(ak + 3) * 132 + arow] = bv.w;
    }
    __syncthreads();

    const int cr = tid >> 4;
    const int cc = tid & 15;
    const int r0 = cr * 4;
    const int c0 = cc * 4;

    float acc[8][8];
#pragma unroll
    for (int i = 0; i < 8; i++)
#pragma unroll
        for (int j = 0; j < 8; j++) acc[i][j] = 0.0f;

    int buf = 0;
    for (int kt = 8; kt <= 384; kt += 8) {
        const bool more = (kt < 384);
        float4 na, nb;
        if (more) {
            na = *(const float4*)(aptr + kt);
            nb = *(const float4*)(bptr + kt);
        }
#pragma unroll
        for (int k = 0; k < 8; k++) {
            float4 a0 = *(const float4*)&As[buf][k * 132 + r0];
            float4 a1 = *(const float4*)&As[buf][k * 132 + r0 + 64];
            float4 b0 = *(const float4*)&Bs[buf][k * 132 + c0];
            float4 b1 = *(const float4*)&Bs[buf][k * 132 + c0 + 64];
            float ar[8] = {a0.x, a0.y, a0.z, a0.w, a1.x, a1.y, a1.z, a1.w};
            float br[8] = {b0.x, b0.y, b0.z, b0.w, b1.x, b1.y, b1.z, b1.w};
#pragma unroll
            for (int i = 0; i < 8; i++)
#pragma unroll
                for (int j = 0; j < 8; j++) acc[i][j] += ar[i] * br[j];
        }
        if (more) {
            int nbuf = buf ^ 1;
            As[nbuf][(ak + 0) * 132 + arow] = na.x;
            As[nbuf][(ak + 1) * 132 + arow] = na.y;
            As[nbuf][(ak + 2) * 132 + arow] = na.z;
            As[nbuf][(ak + 3) * 132 + arow] = na.w;
            Bs[nbuf][(ak + 0) * 132 + arow] = nb.x;
            Bs[nbuf][(ak + 1) * 132 + arow] = nb.y;
            Bs[nbuf][(ak + 2) * 132 + arow] = nb.z;
            Bs[nbuf][(ak + 3) * 132 + arow] = nb.w;
            __syncthreads();
            buf = nbuf;
        }
    }

#pragma unroll
    for (int ii = 0; ii < 8; ii++) {
        int row = r0 + (ii & 3) + ((ii >> 2) << 6);
        int m = by * 128 + row;
        int win = 0, n = 0;
        if (MODE == 0) { win = m / 49; n = m - win * 49; }
#pragma unroll
        for (int jj = 0; jj < 2; jj++) {
            int oc = bx * 128 + c0 + jj * 64;
            float4 bb = *(const float4*)&bias[oc];
            float4 o;
            o.x = acc[ii][jj * 4 + 0] + bb.x;
            o.y = acc[ii][jj * 4 + 1] + bb.y;
            o.z = acc[ii][jj * 4 + 2] + bb.z;
            o.w = acc[ii][jj * 4 + 3] + bb.w;
            if (MODE == 0) {
                int which = oc / 384;
                int remo = oc - which * 384;
                int head = remo >> 5;
                int d0 = remo & 31;
                if (which == 0) {
                    o.x *= Q_SCALE; o.y *= Q_SCALE; o.z *= Q_SCALE; o.w *= Q_SCALE;
                }
                float* dst = g_qkv + (size_t)which * QKV_ONE
                           + ((size_t)(win * 12 + head) * 49 + n) * 32 + d0;
                *(float4*)dst = o;
            } else {
                float* dst = outp + g_rowbase[m] + oc;
                *(float4*)dst = o;
            }
        }
    }
}

// ---------------------------------------------------------------------------
// Per (window, head) attention, register-blocked.
// Warp w owns rows {w + 8t, t=0..6} (<49). S phase: lane registerizes K cols
// j=lane and j=lane+32 (K row stride 36 -> conflict-free float4 column reads).
// SV phase: lane owns d=lane; S read as broadcast float4 (pad cols zeroed).
__global__ __launch_bounds__(256)
void attn_kernel(const float* __restrict__ table)
{
    __shared__ __align__(16) float Qs[1568];        // [49][32]
    __shared__ __align__(16) float Ks[49 * 36];     // [49][36] padded
    __shared__ __align__(16) float Vs[1568];        // [49][32]
    __shared__ __align__(16) float S[49 * 52];      // [49][52] padded
    __shared__ float tbl[169];
    __shared__ int   ids[49];

    const int tid = threadIdx.x;
    const int lane = tid & 31, warp = tid >> 5;
    const int bid = blockIdx.x;
    const int win = bid / 12;          // global window 0..1023
    const int head = bid - win * 12;

    const size_t base = (size_t)bid * 1568;
    const float4* q4 = (const float4*)(g_qkv + base);
    const float4* k4 = (const float4*)(g_qkv + QKV_ONE + base);
    const float4* v4 = (const float4*)(g_qkv + 2 * QKV_ONE + base);
    for (int i = tid; i < 392; i += 256) {
        ((float4*)Qs)[i] = q4[i];
        int row = i >> 3, dc = i & 7;
        *(float4*)&Ks[row * 36 + dc * 4] = k4[i];
        ((float4*)Vs)[i] = v4[i];
    }
    if (tid < 169) tbl[tid] = table[tid * 12 + head];
    if (tid < 49) {
        int winl = win & 63;               // local window within image
        int wi = winl >> 3, wj = winl & 7;
        int r = tid / 7, c = tid - r * 7;
        int hh = wi * 7 + r, ww = wj * 7 + c;
        int rh = (hh < 49) ? 0 : ((hh < 53) ? 1 : 2);
        int rw = (ww < 49) ? 0 : ((ww < 53) ? 1 : 2);
        ids[tid] = rh * 3 + rw;
    }
    __syncthreads();

    // ---- S = Q K^T (register-blocked) ----
    const int jA = lane;           // < 49 always
    const int jB = lane + 32;      // valid if < 49
    const bool hasB = (jB < 49);
    float accA[7], accB[7];
#pragma unroll
    for (int t = 0; t < 7; t++) { accA[t] = 0.0f; accB[t] = 0.0f; }

#pragma unroll
    for (int half = 0; half < 2; half++) {
        const int d0 = half * 16;
        float4 kA[4], kB[4];
#pragma unroll
        for (int q = 0; q < 4; q++) {
            kA[q] = *(const float4*)&Ks[jA * 36 + d0 + q * 4];
            kB[q] = hasB ? *(const float4*)&Ks[jB * 36 + d0 + q * 4]
                         : make_float4(0.f, 0.f, 0.f, 0.f);
        }
#pragma unroll
        for (int t = 0; t < 7; t++) {
            int row = warp + 8 * t;
            if (row < 49) {
#pragma unroll
                for (int q = 0; q < 4; q++) {
                    float4 qv = *(const float4*)&Qs[row * 32 + d0 + q * 4];
                    accA[t] += qv.x * kA[q].x + qv.y * kA[q].y
                             + qv.z * kA[q].z + qv.w * kA[q].w;
                    accB[t] += qv.x * kB[q].x + qv.y * kB[q].y
                             + qv.z * kB[q].z + qv.w * kB[q].w;
                }
            }
        }
    }

    // bias + mask + store (zero pad cols 49..51)
#pragma unroll
    for (int t = 0; t < 7; t++) {
        int row = warp + 8 * t;
        if (row < 49) {
            int r1 = row / 7, c1 = row - r1 * 7;
            {
                int r2 = jA / 7, c2 = jA - r2 * 7;
                float s = accA[t] + tbl[(r1 - r2 + 6) * 13 + (c1 - c2 + 6)];
                if (ids[row] != ids[jA]) s -= 100.0f;
                S[row * 52 + jA] = s;
            }
            if (hasB) {
                int r2 = jB / 7, c2 = jB - r2 * 7;
                float s = accB[t] + tbl[(r1 - r2 + 6) * 13 + (c1 - c2 + 6)];
                if (ids[row] != ids[jB]) s -= 100.0f;
                S[row * 52 + jB] = s;
            } else if (jB < 52) {
                S[row * 52 + jB] = 0.0f;   // pad col, stays 0 through softmax
            }
        }
    }
    __syncthreads();

    // ---- softmax: one warp per row (rows warp, warp+8, ...) ----
    for (int row = warp; row < 49; row += 8) {
        float v0 = S[row * 52 + lane];
        float v1 = (lane < 17) ? S[row * 52 + 32 + lane] : -1e30f;
        float mx = fmaxf(v0, v1);
#pragma unroll
        for (int off = 16; off; off >>= 1)
            mx = fmaxf(mx, __shfl_xor_sync(0xffffffffu, mx, off));
        float e0 = __expf(v0 - mx);
        float e1 = (lane < 17) ? __expf(v1 - mx) : 0.0f;
        float sm = e0 + e1;
#pragma unroll
        for (int off = 16; off; off >>= 1)
            sm += __shfl_xor_sync(0xffffffffu, sm, off);
        float inv = 1.0f / sm;
        S[row * 52 + lane] = e0 * inv;
        if (lane < 17) S[row * 52 + 32 + lane] = e1 * inv;
    }
    __syncthreads();

    // ---- O = S V (register-blocked), lane owns d = lane ----
    float o[7];
#pragma unroll
    for (int t = 0; t < 7; t++) o[t] = 0.0f;

#pragma unroll
    for (int jc = 0; jc < 52; jc += 4) {
        float v0 = Vs[(jc + 0) * 32 + lane];
        float v1 = (jc + 1 < 49) ? Vs[(jc + 1) * 32 + lane] : 0.0f;
        float v2 = (jc + 2 < 49) ? Vs[(jc + 2) * 32 + lane] : 0.0f;
        float v3 = (jc + 3 < 49) ? Vs[(jc + 3) * 32 + lane] : 0.0f;
#pragma unroll
        for (int t = 0; t < 7; t++) {
            int row = warp + 8 * t;
            if (row < 49) {
                float4 s4 = *(const float4*)&S[row * 52 + jc];
                o[t] += s4.x * v0 + s4.y * v1 + s4.z * v2 + s4.w * v3;
            }
        }
    }
#pragma unroll
    for (int t = 0; t < 7; t++) {
        int row = warp + 8 * t;
        if (row < 49)
            g_attn[((size_t)win * 49 + row) * 384 + head * 32 + lane] = o[t];
    }
}

// ---------------------------------------------------------------------------
extern "C" void kernel_launch(void* const* d_in, const int* in_sizes, int n_in,
                              void* d_out, int out_size)
{
    const float* x      = (const float*)d_in[0];
    const float* qkv_w  = (const float*)d_in[1];
    const float* qkv_b  = (const float*)d_in[2];
    const float* proj_w = (const float*)d_in[3];
    const float* proj_b = (const float*)d_in[4];
    const float* table  = (const float*)d_in[5];
    float* out = (float*)d_out;

    setup_kernel<<<(M_TOT + 255) / 256, 256>>>();
    gemm_kernel<0><<<dim3(9, 392), 256>>>(x, qkv_w, qkv_b, nullptr);
    attn_kernel<<<12288, 256>>>(table);
    gemm_kernel<1><<<dim3(3, 392), 256>>>(nullptr, proj_w, proj_b, out);
}